// round 14
// baseline (speedup 1.0000x reference)
#include <cuda_runtime.h>
#include <cuda_bf16.h>
#include <cstdint>

#define NN 50000
#define EE 500000
#define F_IN 64
#define E_IN 16
#define HH 100
#define NL 2

__device__ float g_buf_node[6u * 5000000u];
__device__ float g_buf_edge[2u * 50000000u];
__device__ float g_stats[256];

// pack 2 floats -> bf16x2 hi and lo words (3-term split source)
__device__ __forceinline__ void split2(float a0, float a1, uint32_t& hw, uint32_t& lw)
{
    __nv_bfloat16 h0 = __float2bfloat16(a0);
    __nv_bfloat16 h1 = __float2bfloat16(a1);
    __nv_bfloat16 l0 = __float2bfloat16(a0 - __bfloat162float(h0));
    __nv_bfloat16 l1 = __float2bfloat16(a1 - __bfloat162float(h1));
    hw = (uint32_t)__bfloat16_as_ushort(h0) | ((uint32_t)__bfloat16_as_ushort(h1) << 16);
    lw = (uint32_t)__bfloat16_as_ushort(l0) | ((uint32_t)__bfloat16_as_ushort(l1) << 16);
}

// m16n8k16 bf16 MMA, fp32 accumulate (baseline PTX, sm_80+; HMMA on sm_103a)
__device__ __forceinline__ void mma16816(float* c, const uint32_t* a, const uint32_t* b)
{
    asm volatile(
        "mma.sync.aligned.m16n8k16.row.col.f32.bf16.bf16.f32 "
        "{%0,%1,%2,%3}, {%4,%5,%6,%7}, {%8,%9}, {%0,%1,%2,%3};"
        : "+f"(c[0]), "+f"(c[1]), "+f"(c[2]), "+f"(c[3])
        : "r"(a[0]), "r"(a[1]), "r"(a[2]), "r"(a[3]), "r"(b[0]), "r"(b[1]));
}

// =============== bf16 3-term split GEMM via mma.sync (K<=128, M-tile 128) ==========
// modes: 0 C=acc+b; 1 relu; 2 relu(acc+b+P[src]+Q[dst]); 3 C+=0.5*(acc+b)
// smem: AH/AL [128][65] u32 (bf16x2), BH/BL [NPAD][65] u32; stage overlaps.
template <int NPAD>
struct TCfg {
    static constexpr int KW   = 65;                        // word stride (odd)
    static constexpr int SMEM = (256 + 2 * NPAD) * KW * 4; // AH+AL+BH+BL
};

template <int NPAD>
__global__ __launch_bounds__(256) void tc_gemm(
    const float* __restrict__ A, const float* __restrict__ B,
    float* __restrict__ C, const float* __restrict__ bias,
    int M, int N, int K, int lda, int ldb, int ldc, int mode,
    const int* __restrict__ src, const int* __restrict__ dst,
    const float* __restrict__ P, const float* __restrict__ Q, int ldpq)
{
    extern __shared__ char smem[];
    constexpr int KW = TCfg<NPAD>::KW;
    constexpr int NAT = NPAD / 8;
    uint32_t* AH = (uint32_t*)smem;
    uint32_t* AL = AH + 128 * KW;
    uint32_t* BH = AL + 128 * KW;
    uint32_t* BL = BH + NPAD * KW;

    const int tid = threadIdx.x, wid = tid >> 5, lane = tid & 31;
    const int row0 = blockIdx.x * 128;

    // ---- fill A (hi & lo), zero-padded: 2048 chunks of 8 k-values ----
#pragma unroll
    for (int it = 0; it < 8; it++) {
        int c = tid + it * 256;
        int rl = c >> 4, kc = (c & 15) * 8;
        int r = row0 + rl;
        float v[8];
#pragma unroll
        for (int j = 0; j < 8; j++) v[j] = 0.f;
        if (r < M) {
            const float* ap = A + (size_t)r * lda;
            if (((lda & 3) == 0) && kc + 7 < K) {
                float4 t0 = *(const float4*)(ap + kc);
                float4 t1 = *(const float4*)(ap + kc + 4);
                v[0] = t0.x; v[1] = t0.y; v[2] = t0.z; v[3] = t0.w;
                v[4] = t1.x; v[5] = t1.y; v[6] = t1.z; v[7] = t1.w;
            } else {
#pragma unroll
                for (int j = 0; j < 8; j++) if (kc + j < K) v[j] = ap[kc + j];
            }
        }
        int base = rl * KW + (kc >> 1);
#pragma unroll
        for (int j = 0; j < 4; j++) {
            uint32_t hw, lw;
            split2(v[2 * j], v[2 * j + 1], hw, lw);
            AH[base + j] = hw; AL[base + j] = lw;
        }
    }

    // ---- fill B [K,N] row-major -> [n][k] pairs (hi & lo), zero-padded ----
    for (int c = tid; c < NPAD * 16; c += 256) {
        int n = c % NPAD, kc = (c / NPAD) * 8;
        float v[8];
#pragma unroll
        for (int j = 0; j < 8; j++) v[j] = 0.f;
        if (n < N) {
#pragma unroll
            for (int j = 0; j < 8; j++)
                if (kc + j < K) v[j] = B[(size_t)(kc + j) * ldb + n];
        }
        int base = n * KW + (kc >> 1);
#pragma unroll
        for (int j = 0; j < 4; j++) {
            uint32_t hw, lw;
            split2(v[2 * j], v[2 * j + 1], hw, lw);
            BH[base + j] = hw; BL[base + j] = lw;
        }
    }
    __syncthreads();

    // ---- MMA mainloop: warp handles rows [wid*16, wid*16+16) x all N ----
    float acc[NAT][4];
#pragma unroll
    for (int na = 0; na < NAT; na++)
#pragma unroll
        for (int j = 0; j < 4; j++) acc[na][j] = 0.f;

    const int ksteps = (K + 15) >> 4;
    const int ra = wid * 16 + (lane >> 2);
    for (int ks = 0; ks < ksteps; ks++) {
        int kw = ks * 8 + (lane & 3);
        uint32_t ah[4], al4[4];
        ah[0] = AH[ra * KW + kw];        ah[1] = AH[(ra + 8) * KW + kw];
        ah[2] = AH[ra * KW + kw + 4];    ah[3] = AH[(ra + 8) * KW + kw + 4];
        al4[0] = AL[ra * KW + kw];       al4[1] = AL[(ra + 8) * KW + kw];
        al4[2] = AL[ra * KW + kw + 4];   al4[3] = AL[(ra + 8) * KW + kw + 4];
#pragma unroll
        for (int na = 0; na < NAT; na++) {
            int nb = na * 8 + (lane >> 2);
            uint32_t bh2[2], bl2[2];
            bh2[0] = BH[nb * KW + kw];  bh2[1] = BH[nb * KW + kw + 4];
            bl2[0] = BL[nb * KW + kw];  bl2[1] = BL[nb * KW + kw + 4];
            mma16816(acc[na], ah, bh2);
            mma16816(acc[na], ah, bl2);
            mma16816(acc[na], al4, bh2);
        }
    }
    __syncthreads();

    // ---- stage accumulators to smem (reuse A/B region), then fused write ----
    const int stride = NPAD + 1;
    float* stage = (float*)smem;
    {
        int cc0 = (lane & 3) * 2;
#pragma unroll
        for (int na = 0; na < NAT; na++) {
            int cc = na * 8 + cc0;
            stage[ra * stride + cc]           = acc[na][0];
            stage[ra * stride + cc + 1]       = acc[na][1];
            stage[(ra + 8) * stride + cc]     = acc[na][2];
            stage[(ra + 8) * stride + cc + 1] = acc[na][3];
        }
    }
    __syncthreads();

    const int total = 128 * N;
    for (int i = tid; i < total; i += 256) {
        int r = i / N, c = i - r * N;
        int gr = row0 + r;
        if (gr < M) {
            float v = stage[r * stride + c] + (bias ? bias[c] : 0.f);
            float* crow = C + (size_t)gr * ldc;
            if (mode == 2) {
                int s = src[gr], dd = dst[gr];
                v += P[(size_t)s * ldpq + c] + Q[(size_t)dd * ldpq + c];
                crow[c] = fmaxf(v, 0.f);
            } else if (mode == 3) {
                crow[c] += 0.5f * v;
            } else if (mode == 1) {
                crow[c] = fmaxf(v, 0.f);
            } else {
                crow[c] = v;
            }
        }
    }
}

// ---------------- elementwise / graph kernels ----------------
__global__ void copy_kernel(float* __restrict__ d_, const float* __restrict__ s_, int n)
{
    int i = blockIdx.x * blockDim.x + threadIdx.x;
    if (i < n) d_[i] = s_[i];
}

__global__ void scatter_kernel(const float* __restrict__ h, const float* __restrict__ e,
                               const int* __restrict__ src, const int* __restrict__ dst,
                               float* __restrict__ agg)
{
    int idx = blockIdx.x * blockDim.x + threadIdx.x;
    if (idx >= EE * 25) return;
    int edge = idx / 25, j = idx % 25;
    int s = src[edge], d = dst[edge];
    float4 ev = reinterpret_cast<const float4*>(e)[edge * 25 + j];
    float4 hv = reinterpret_cast<const float4*>(h)[(size_t)s * 25 + j];
    float4 m;
    m.x = fmaxf(ev.x + hv.x, 0.f);
    m.y = fmaxf(ev.y + hv.y, 0.f);
    m.z = fmaxf(ev.z + hv.z, 0.f);
    m.w = fmaxf(ev.w + hv.w, 0.f);
    atomicAdd(reinterpret_cast<float4*>(agg + (size_t)d * HH) + j, m);
}

__global__ void bn_stats_kernel(const float* __restrict__ z, float* __restrict__ mean,
                                float* __restrict__ rstd)
{
    __shared__ float sh[256], sh2[256];
    int c = blockIdx.x;
    float s = 0.f, s2 = 0.f;
    for (int r = threadIdx.x; r < NN; r += 256) {
        float v = z[(size_t)r * HH + c];
        s += v; s2 += v * v;
    }
    sh[threadIdx.x] = s; sh2[threadIdx.x] = s2;
    __syncthreads();
    for (int o = 128; o > 0; o >>= 1) {
        if (threadIdx.x < o) { sh[threadIdx.x] += sh[threadIdx.x + o]; sh2[threadIdx.x] += sh2[threadIdx.x + o]; }
        __syncthreads();
    }
    if (threadIdx.x == 0) {
        float mu = sh[0] / (float)NN;
        float var = sh2[0] / (float)NN - mu * mu;
        mean[c] = mu;
        rstd[c] = rsqrtf(fmaxf(var, 0.f) + 1e-5f);
    }
}

__global__ void h_update_kernel(float* __restrict__ h, const float* __restrict__ z,
                                const float* __restrict__ mean, const float* __restrict__ rstd,
                                const float* __restrict__ gamma, const float* __restrict__ beta, int n)
{
    int i = blockIdx.x * blockDim.x + threadIdx.x;
    if (i >= n) return;
    int c = i % HH;
    float zn = (z[i] - mean[c]) * rstd[c] * gamma[c] + beta[c];
    h[i] = (h[i] + fmaxf(zn, 0.f)) * 0.5f;
}

__global__ void relu_copy_kernel(float* __restrict__ d_, const float* __restrict__ s_, int n)
{
    int i = blockIdx.x * blockDim.x + threadIdx.x;
    if (i < n) d_[i] = fmaxf(s_[i], 0.f);
}

__global__ void out_kernel(const float* __restrict__ o2, const float* __restrict__ w3,
                           const float* __restrict__ b3, float* __restrict__ out)
{
    __shared__ float w[50], b[2];
    if (threadIdx.x < 50) w[threadIdx.x] = w3[threadIdx.x];
    if (threadIdx.x < 2) b[threadIdx.x] = b3[threadIdx.x];
    __syncthreads();
    int eIdx = blockIdx.x * blockDim.x + threadIdx.x;
    if (eIdx >= EE) return;
    float a0 = b[0], a1 = b[1];
    const float* row = o2 + (size_t)eIdx * 25;
#pragma unroll
    for (int k = 0; k < 25; k++) {
        float v = row[k];
        a0 = fmaf(v, w[2 * k], a0);
        a1 = fmaf(v, w[2 * k + 1], a1);
    }
    out[eIdx * 2] = a0;
    out[eIdx * 2 + 1] = a1;
}

// ---------------- host ----------------
template <int NPAD>
static void launch_tc(const float* A, const float* B, float* C, const float* bias,
                      int M, int N, int K, int lda, int ldb, int ldc, int mode,
                      const int* src = nullptr, const int* dst = nullptr,
                      const float* P = nullptr, const float* Q = nullptr, int ldpq = 0)
{
    cudaFuncSetAttribute(tc_gemm<NPAD>, cudaFuncAttributeMaxDynamicSharedMemorySize, TCfg<NPAD>::SMEM);
    tc_gemm<NPAD><<<(M + 127) / 128, 256, TCfg<NPAD>::SMEM>>>(
        A, B, C, bias, M, N, K, lda, ldb, ldc, mode, src, dst, P, Q, ldpq);
}

extern "C" void kernel_launch(void* const* d_in, const int* in_sizes, int n_in,
                              void* d_out, int out_size)
{
    const float* x       = (const float*)d_in[0];
    const float* ea      = (const float*)d_in[1];
    const int*   ei      = (const int*)d_in[2];
    const float* node_w  = (const float*)d_in[3];
    const float* node_b  = (const float*)d_in[4];
    const float* edge_w  = (const float*)d_in[5];
    const float* edge_b  = (const float*)d_in[6];
    const float* gine_w1 = (const float*)d_in[7];
    const float* gine_b1 = (const float*)d_in[8];
    const float* gine_w2 = (const float*)d_in[9];
    const float* gine_b2 = (const float*)d_in[10];
    const float* bn_g    = (const float*)d_in[11];
    const float* bn_b    = (const float*)d_in[12];
    const float* emlp_w1 = (const float*)d_in[13];
    const float* emlp_b1 = (const float*)d_in[14];
    const float* emlp_w2 = (const float*)d_in[15];
    const float* emlp_b2 = (const float*)d_in[16];
    const float* mlp_w1  = (const float*)d_in[17];
    const float* mlp_b1  = (const float*)d_in[18];
    const float* mlp_w2  = (const float*)d_in[19];
    const float* mlp_b2  = (const float*)d_in[20];
    const float* mlp_w3  = (const float*)d_in[21];
    const float* mlp_b3  = (const float*)d_in[22];

    void* pv;
    cudaGetSymbolAddress(&pv, g_buf_node);
    float* nb = (float*)pv;
    float* h   = nb;
    float* agg = nb + 1u * 5000000u;
    float* t1  = nb + 2u * 5000000u;
    float* P   = nb + 3u * 5000000u;
    float* Q   = nb + 4u * 5000000u;
    float* z2  = nb + 5u * 5000000u;
    cudaGetSymbolAddress(&pv, g_buf_edge);
    float* eb = (float*)pv;
    float* e    = eb;
    float* tbuf = eb + 1u * 50000000u;
    cudaGetSymbolAddress(&pv, g_stats);
    float* mean = (float*)pv;
    float* rstd = mean + 128;

    const int* src = ei;
    const int* dst = ei + EE;

    const int NH = NN * HH;
    const int ECH = EE * 25;
    dim3 blk(256);
    int gNH = (NH + 255) / 256;
    int gECH = (ECH + 255) / 256;

    // embeddings
    launch_tc<104>(x, node_w, h, node_b, NN, HH, F_IN, F_IN, HH, HH, 0);
    launch_tc<104>(ea, edge_w, e, edge_b, EE, HH, E_IN, E_IN, HH, HH, 0);

    for (int i = 0; i < NL; i++) {
        const float* gw1 = gine_w1 + i * HH * HH;
        const float* gb1 = gine_b1 + i * HH;
        const float* gw2 = gine_w2 + i * HH * HH;
        const float* gb2 = gine_b2 + i * HH;
        const float* ew1 = emlp_w1 + i * 3 * HH * HH;
        const float* eb1 = emlp_b1 + i * HH;
        const float* ew2 = emlp_w2 + i * HH * HH;
        const float* eb2 = emlp_b2 + i * HH;

        // agg = h; agg[dst] += relu(h[src]+e)  (=> z)
        copy_kernel<<<gNH, blk>>>(agg, h, NH);
        scatter_kernel<<<gECH, blk>>>(h, e, src, dst, agg);

        // GINE node MLP
        launch_tc<104>(agg, gw1, t1, gb1, NN, HH, HH, HH, HH, HH, 1);
        launch_tc<104>(t1, gw2, z2, gb2, NN, HH, HH, HH, HH, HH, 0);

        // batchnorm + h update
        bn_stats_kernel<<<HH, blk>>>(z2, mean, rstd);
        h_update_kernel<<<gNH, blk>>>(h, z2, mean, rstd, bn_g + i * HH, bn_b + i * HH, NH);

        // edge MLP (factored cat@W1)
        launch_tc<104>(h, ew1,            P, nullptr, NN, HH, HH, HH, HH, HH, 0);
        launch_tc<104>(h, ew1 + 100 * HH, Q, nullptr, NN, HH, HH, HH, HH, HH, 0);
        launch_tc<104>(e, ew1 + 200 * HH, tbuf, eb1, EE, HH, HH, HH, HH, HH, 2, src, dst, P, Q, HH);
        launch_tc<104>(tbuf, ew2, e, eb2, EE, HH, HH, HH, HH, HH, 3);
    }

    // readout (factored)
    relu_copy_kernel<<<gNH, blk>>>(t1, h, NH);
    launch_tc<56>(t1, mlp_w1,            P, nullptr, NN, 50, HH, HH, 50, 50, 0);
    launch_tc<56>(t1, mlp_w1 + 100 * 50, Q, nullptr, NN, 50, HH, HH, 50, 50, 0);
    launch_tc<56>(e, mlp_w1 + 200 * 50, tbuf, mlp_b1, EE, 50, HH, HH, 50, 50, 2, src, dst, P, Q, 50);
    launch_tc<32>(tbuf, mlp_w2, tbuf + 25000000u, mlp_b2, EE, 25, 50, 50, 25, 25, 1);
    out_kernel<<<(EE + 255) / 256, blk>>>(tbuf + 25000000u, mlp_w3, mlp_b3, (float*)d_out);
}

// round 15
// speedup vs baseline: 1.3912x; 1.3912x over previous
#include <cuda_runtime.h>
#include <cuda_bf16.h>

// Problem constants
#define NN 50000
#define EE 500000
#define F_IN 64
#define E_IN 16
#define HH 100
#define NL 2

__device__ float g_buf_node[6u * 5000000u];
__device__ float g_buf_edge[2u * 50000000u];
__device__ float g_stats[256];

// ---------------------------------------------------------------------------
// fp32 tiled GEMM, double-buffered smem, fused epilogues.
// C[M,N] = A[M,K] @ B[K,N], tile 128x128, K-chunk 16, 256 thr, 8x8/thr.
// mode 0: C = acc + bias      1: relu(acc + bias)
// mode 2: C = relu(acc + P[src[r]] + Q[dst[r]] + bias)
// mode 3: C += 0.5*(acc + bias)
// ---------------------------------------------------------------------------
__global__ __launch_bounds__(256) void sgemm_kernel(
    const float* __restrict__ A, const float* __restrict__ B,
    float* __restrict__ C, const float* __restrict__ bias,
    int M, int N, int K, int lda, int ldb, int ldc, int mode,
    const int* __restrict__ src, const int* __restrict__ dst,
    const float* __restrict__ P, const float* __restrict__ Q, int ldpq)
{
    __shared__ float As[2][16][128];
    __shared__ float Bs[2][16][128];

    const int t = threadIdx.x;
    const int tx = t & 15;
    const int ty = t >> 4;
    const int row0 = blockIdx.y * 128;
    const int col0 = blockIdx.x * 128;

    const int a_m = t >> 1;          // 0..127
    const int a_k = (t & 1) * 8;     // 0 or 8
    const int b_k = t >> 4;          // 0..15
    const int b_n = (t & 15) * 8;    // 0..120
    const int arow = row0 + a_m;

    float acc[8][8];
#pragma unroll
    for (int i = 0; i < 8; i++)
#pragma unroll
        for (int j = 0; j < 8; j++) acc[i][j] = 0.f;

    float ra[8], rb[8];
    const int nchunk = (K + 15) >> 4;

    // fetch chunk 0 -> regs
    {
        const int k0 = 0;
#pragma unroll
        for (int i = 0; i < 8; i++) {
            int k = k0 + a_k + i;
            ra[i] = (arow < M && k < K) ? A[(size_t)arow * lda + k] : 0.f;
        }
        int kb = k0 + b_k;
#pragma unroll
        for (int i = 0; i < 8; i++) {
            int n = col0 + b_n + i;
            rb[i] = (kb < K && n < N) ? B[(size_t)kb * ldb + n] : 0.f;
        }
    }
    // store chunk 0 -> buf 0
#pragma unroll
    for (int i = 0; i < 8; i++) As[0][a_k + i][a_m] = ra[i];
#pragma unroll
    for (int i = 0; i < 8; i++) Bs[0][b_k][b_n + i] = rb[i];
    __syncthreads();

    for (int c = 0; c < nchunk; c++) {
        const int buf = c & 1;
        const bool more = (c + 1 < nchunk);
        if (more) {
            const int k0 = (c + 1) * 16;
#pragma unroll
            for (int i = 0; i < 8; i++) {
                int k = k0 + a_k + i;
                ra[i] = (arow < M && k < K) ? A[(size_t)arow * lda + k] : 0.f;
            }
            int kb = k0 + b_k;
#pragma unroll
            for (int i = 0; i < 8; i++) {
                int n = col0 + b_n + i;
                rb[i] = (kb < K && n < N) ? B[(size_t)kb * ldb + n] : 0.f;
            }
        }
        // compute on buf (hides the LDGs above)
#pragma unroll
        for (int kk = 0; kk < 16; kk++) {
            float a[8], b[8];
#pragma unroll
            for (int i = 0; i < 8; i++) a[i] = As[buf][kk][ty * 8 + i];
#pragma unroll
            for (int j = 0; j < 8; j++) b[j] = Bs[buf][kk][tx * 8 + j];
#pragma unroll
            for (int i = 0; i < 8; i++)
#pragma unroll
                for (int j = 0; j < 8; j++)
                    acc[i][j] = fmaf(a[i], b[j], acc[i][j]);
        }
        if (more) {
            const int nb = buf ^ 1;   // last read in iteration c-1; safe to overwrite
#pragma unroll
            for (int i = 0; i < 8; i++) As[nb][a_k + i][a_m] = ra[i];
#pragma unroll
            for (int i = 0; i < 8; i++) Bs[nb][b_k][b_n + i] = rb[i];
        }
        __syncthreads();
    }

    float bv[8];
#pragma unroll
    for (int j = 0; j < 8; j++) {
        int cc = col0 + tx * 8 + j;
        bv[j] = (bias && cc < N) ? bias[cc] : 0.f;
    }

#pragma unroll
    for (int i = 0; i < 8; i++) {
        int r = row0 + ty * 8 + i;
        if (r >= M) continue;
        float* crow = C + (size_t)r * ldc;
        if (mode == 2) {
            int s = src[r], d = dst[r];
            const float* prow = P + (size_t)s * ldpq;
            const float* qrow = Q + (size_t)d * ldpq;
#pragma unroll
            for (int j = 0; j < 8; j++) {
                int cc = col0 + tx * 8 + j;
                if (cc >= N) continue;
                float v = acc[i][j] + bv[j] + prow[cc] + qrow[cc];
                crow[cc] = fmaxf(v, 0.f);
            }
        } else if (mode == 3) {
#pragma unroll
            for (int j = 0; j < 8; j++) {
                int cc = col0 + tx * 8 + j;
                if (cc >= N) continue;
                crow[cc] += 0.5f * (acc[i][j] + bv[j]);
            }
        } else {
#pragma unroll
            for (int j = 0; j < 8; j++) {
                int cc = col0 + tx * 8 + j;
                if (cc >= N) continue;
                float v = acc[i][j] + bv[j];
                if (mode == 1) v = fmaxf(v, 0.f);
                crow[cc] = v;
            }
        }
    }
}

// ---------------------------------------------------------------------------
// Elementwise / graph kernels
// ---------------------------------------------------------------------------
__global__ void copy_kernel(float* __restrict__ dst_, const float* __restrict__ src_, int n)
{
    int i = blockIdx.x * blockDim.x + threadIdx.x;
    if (i < n) dst_[i] = src_[i];
}

// msg = relu(h[src] + e); agg[dst] += msg   (float4 HW atomics, sm_90+)
__global__ void scatter_kernel(const float* __restrict__ h, const float* __restrict__ e,
                               const int* __restrict__ src, const int* __restrict__ dst,
                               float* __restrict__ agg)
{
    int idx = blockIdx.x * blockDim.x + threadIdx.x;
    if (idx >= EE * 25) return;
    int edge = idx / 25, j = idx % 25;
    int s = src[edge], d = dst[edge];
    float4 ev = reinterpret_cast<const float4*>(e)[edge * 25 + j];
    float4 hv = reinterpret_cast<const float4*>(h)[(size_t)s * 25 + j];
    float4 m;
    m.x = fmaxf(ev.x + hv.x, 0.f);
    m.y = fmaxf(ev.y + hv.y, 0.f);
    m.z = fmaxf(ev.z + hv.z, 0.f);
    m.w = fmaxf(ev.w + hv.w, 0.f);
    atomicAdd(reinterpret_cast<float4*>(agg + (size_t)d * HH) + j, m);
}

__global__ void bn_stats_kernel(const float* __restrict__ z, float* __restrict__ mean,
                                float* __restrict__ rstd)
{
    __shared__ float sh[256], sh2[256];
    int c = blockIdx.x;
    float s = 0.f, s2 = 0.f;
    for (int r = threadIdx.x; r < NN; r += 256) {
        float v = z[(size_t)r * HH + c];
        s += v; s2 += v * v;
    }
    sh[threadIdx.x] = s; sh2[threadIdx.x] = s2;
    __syncthreads();
    for (int o = 128; o > 0; o >>= 1) {
        if (threadIdx.x < o) { sh[threadIdx.x] += sh[threadIdx.x + o]; sh2[threadIdx.x] += sh2[threadIdx.x + o]; }
        __syncthreads();
    }
    if (threadIdx.x == 0) {
        float mu = sh[0] / (float)NN;
        float var = sh2[0] / (float)NN - mu * mu;
        mean[c] = mu;
        rstd[c] = rsqrtf(fmaxf(var, 0.f) + 1e-5f);
    }
}

__global__ void h_update_kernel(float* __restrict__ h, const float* __restrict__ z,
                                const float* __restrict__ mean, const float* __restrict__ rstd,
                                const float* __restrict__ gamma, const float* __restrict__ beta, int n)
{
    int i = blockIdx.x * blockDim.x + threadIdx.x;
    if (i >= n) return;
    int c = i % HH;
    float zn = (z[i] - mean[c]) * rstd[c] * gamma[c] + beta[c];
    h[i] = (h[i] + fmaxf(zn, 0.f)) * 0.5f;
}

__global__ void relu_copy_kernel(float* __restrict__ dst_, const float* __restrict__ src_, int n)
{
    int i = blockIdx.x * blockDim.x + threadIdx.x;
    if (i < n) dst_[i] = fmaxf(src_[i], 0.f);
}

__global__ void out_kernel(const float* __restrict__ o2, const float* __restrict__ w3,
                           const float* __restrict__ b3, float* __restrict__ out)
{
    __shared__ float w[50], b[2];
    if (threadIdx.x < 50) w[threadIdx.x] = w3[threadIdx.x];
    if (threadIdx.x < 2) b[threadIdx.x] = b3[threadIdx.x];
    __syncthreads();
    int eIdx = blockIdx.x * blockDim.x + threadIdx.x;
    if (eIdx >= EE) return;
    float a0 = b[0], a1 = b[1];
    const float* row = o2 + (size_t)eIdx * 25;
#pragma unroll
    for (int k = 0; k < 25; k++) {
        float v = row[k];
        a0 = fmaf(v, w[2 * k], a0);
        a1 = fmaf(v, w[2 * k + 1], a1);
    }
    out[eIdx * 2] = a0;
    out[eIdx * 2 + 1] = a1;
}

// ---------------------------------------------------------------------------
// Host launcher
// ---------------------------------------------------------------------------
static inline void launch_gemm(const float* A, const float* B, float* C, const float* bias,
                               int M, int N, int K, int lda, int ldb, int ldc, int mode,
                               const int* src = nullptr, const int* dst = nullptr,
                               const float* P = nullptr, const float* Q = nullptr, int ldpq = 0)
{
    dim3 grid((N + 127) / 128, (M + 127) / 128);
    sgemm_kernel<<<grid, 256>>>(A, B, C, bias, M, N, K, lda, ldb, ldc, mode,
                                src, dst, P, Q, ldpq);
}

extern "C" void kernel_launch(void* const* d_in, const int* in_sizes, int n_in,
                              void* d_out, int out_size)
{
    const float* x       = (const float*)d_in[0];
    const float* ea      = (const float*)d_in[1];
    const int*   ei      = (const int*)d_in[2];
    const float* node_w  = (const float*)d_in[3];
    const float* node_b  = (const float*)d_in[4];
    const float* edge_w  = (const float*)d_in[5];
    const float* edge_b  = (const float*)d_in[6];
    const float* gine_w1 = (const float*)d_in[7];
    const float* gine_b1 = (const float*)d_in[8];
    const float* gine_w2 = (const float*)d_in[9];
    const float* gine_b2 = (const float*)d_in[10];
    const float* bn_g    = (const float*)d_in[11];
    const float* bn_b    = (const float*)d_in[12];
    const float* emlp_w1 = (const float*)d_in[13];
    const float* emlp_b1 = (const float*)d_in[14];
    const float* emlp_w2 = (const float*)d_in[15];
    const float* emlp_b2 = (const float*)d_in[16];
    const float* mlp_w1  = (const float*)d_in[17];
    const float* mlp_b1  = (const float*)d_in[18];
    const float* mlp_w2  = (const float*)d_in[19];
    const float* mlp_b2  = (const float*)d_in[20];
    const float* mlp_w3  = (const float*)d_in[21];
    const float* mlp_b3  = (const float*)d_in[22];

    void* pv;
    cudaGetSymbolAddress(&pv, g_buf_node);
    float* nb = (float*)pv;
    float* h   = nb;
    float* agg = nb + 1u * 5000000u;
    float* t1  = nb + 2u * 5000000u;
    float* P   = nb + 3u * 5000000u;
    float* Q   = nb + 4u * 5000000u;
    float* z2  = nb + 5u * 5000000u;
    cudaGetSymbolAddress(&pv, g_buf_edge);
    float* eb = (float*)pv;
    float* e    = eb;
    float* tbuf = eb + 1u * 50000000u;
    cudaGetSymbolAddress(&pv, g_stats);
    float* mean = (float*)pv;
    float* rstd = mean + 128;

    const int* src = ei;
    const int* dst = ei + EE;

    const int NH = NN * HH;
    const int ECH = EE * 25;
    dim3 blk(256);
    int gNH = (NH + 255) / 256;
    int gECH = (ECH + 255) / 256;

    // embeddings
    launch_gemm(x, node_w, h, node_b, NN, HH, F_IN, F_IN, HH, HH, 0);
    launch_gemm(ea, edge_w, e, edge_b, EE, HH, E_IN, E_IN, HH, HH, 0);

    for (int i = 0; i < NL; i++) {
        const float* gw1 = gine_w1 + i * HH * HH;
        const float* gb1 = gine_b1 + i * HH;
        const float* gw2 = gine_w2 + i * HH * HH;
        const float* gb2 = gine_b2 + i * HH;
        const float* ew1 = emlp_w1 + i * 3 * HH * HH;
        const float* eb1 = emlp_b1 + i * HH;
        const float* ew2 = emlp_w2 + i * HH * HH;
        const float* eb2 = emlp_b2 + i * HH;

        // agg = h; agg[dst] += relu(h[src]+e)  (=> z)
        copy_kernel<<<gNH, blk>>>(agg, h, NH);
        scatter_kernel<<<gECH, blk>>>(h, e, src, dst, agg);

        // GINE node MLP
        launch_gemm(agg, gw1, t1, gb1, NN, HH, HH, HH, HH, HH, 1);
        launch_gemm(t1, gw2, z2, gb2, NN, HH, HH, HH, HH, HH, 0);

        // batchnorm + h update
        bn_stats_kernel<<<HH, blk>>>(z2, mean, rstd);
        h_update_kernel<<<gNH, blk>>>(h, z2, mean, rstd, bn_g + i * HH, bn_b + i * HH, NH);

        // edge MLP (factored cat@W1)
        launch_gemm(h, ew1,            P, nullptr, NN, HH, HH, HH, HH, HH, 0);
        launch_gemm(h, ew1 + 100 * HH, Q, nullptr, NN, HH, HH, HH, HH, HH, 0);
        launch_gemm(e, ew1 + 200 * HH, tbuf, eb1, EE, HH, HH, HH, HH, HH, 2, src, dst, P, Q, HH);
        launch_gemm(tbuf, ew2, e, eb2, EE, HH, HH, HH, HH, HH, 3);
    }

    // readout (factored)
    relu_copy_kernel<<<gNH, blk>>>(t1, h, NH);
    launch_gemm(t1, mlp_w1,            P, nullptr, NN, 50, HH, HH, 50, 50, 0);
    launch_gemm(t1, mlp_w1 + 100 * 50, Q, nullptr, NN, 50, HH, HH, 50, 50, 0);
    launch_gemm(e, mlp_w1 + 200 * 50, tbuf, mlp_b1, EE, 50, HH, HH, 50, 50, 2, src, dst, P, Q, 50);
    launch_gemm(tbuf, mlp_w2, tbuf + 25000000u, mlp_b2, EE, 25, 50, 50, 25, 25, 1);
    out_kernel<<<(EE + 255) / 256, blk>>>(tbuf + 25000000u, mlp_w3, mlp_b3, (float*)d_out);
}